// round 2
// baseline (speedup 1.0000x reference)
#include <cuda_runtime.h>
#include <math.h>

#define NG    2048
#define W     128
#define H     128
#define NPIX  (W*H)
#define EPSV  1e-4f
#define NEARV 0.3f
#define TW    16          // tile width (px)
#define TH    8           // tile height (px)
#define BT    (TW*TH)     // 128 threads per render block
#define NTX   (W/TW)      // 8
#define NTY   (H/TH)      // 16
#define TAU   18.2f       // skip threshold on folded exponent

// ---------------- device scratch ----------------
__device__ float4 d_cull[NG];  // u, v, hx, hy   (conservative AABB half-widths)
__device__ float4 d_ga [NG];   // u, v, A, B     (pw = A dx^2 + B dx dy + C dy^2 + L)
__device__ float4 d_gb [NG];   // C, L, r, g
__device__ float  d_bb [NG];   // b
__device__ float  d_key[NG];   // depth key r (camera-space norm)

__device__ __forceinline__ float sigmoidf_(float x) {
    return 1.0f / (1.0f + expf(-x));
}

// ---------------- 1) per-gaussian preprocessing ----------------
__global__ void prep_kernel(const float* __restrict__ pos,
                            const float* __restrict__ rgb,
                            const float* __restrict__ opa,
                            const float* __restrict__ quat,
                            const float* __restrict__ scale,
                            const float* __restrict__ rot,
                            const float* __restrict__ tran)
{
    int n = blockIdx.x * blockDim.x + threadIdx.x;
    if (n >= NG) return;

    float Rw[9];
#pragma unroll
    for (int i = 0; i < 9; i++) Rw[i] = __ldg(&rot[i]);
    float t0 = __ldg(&tran[0]), t1 = __ldg(&tran[1]), t2 = __ldg(&tran[2]);

    float p0 = pos[n*3+0], p1 = pos[n*3+1], p2 = pos[n*3+2];
    float x = Rw[0]*p0 + Rw[1]*p1 + Rw[2]*p2 + t0;
    float y = Rw[3]*p0 + Rw[4]*p1 + Rw[5]*p2 + t1;
    float z = Rw[6]*p0 + Rw[7]*p1 + Rw[8]*p2 + t2;

    float r = sqrtf(x*x + y*y + z*z);
    float iz  = 1.0f / z;
    float u = x * iz, v = y * iz;
    float iz2 = iz * iz;

    // M = first two rows of J @ rot
    float M00 = iz*Rw[0] - x*iz2*Rw[6];
    float M01 = iz*Rw[1] - x*iz2*Rw[7];
    float M02 = iz*Rw[2] - x*iz2*Rw[8];
    float M10 = iz*Rw[3] - y*iz2*Rw[6];
    float M11 = iz*Rw[4] - y*iz2*Rw[7];
    float M12 = iz*Rw[5] - y*iz2*Rw[8];

    // quaternion -> rotation
    float qw = quat[n*4+0], qx = quat[n*4+1], qy = quat[n*4+2], qz = quat[n*4+3];
    float qn = rsqrtf(qw*qw + qx*qx + qy*qy + qz*qz);
    qw *= qn; qx *= qn; qy *= qn; qz *= qn;
    float R00 = 1.0f - 2.0f*(qy*qy + qz*qz);
    float R01 = 2.0f*(qx*qy - qw*qz);
    float R02 = 2.0f*(qx*qz + qw*qy);
    float R10 = 2.0f*(qx*qy + qw*qz);
    float R11 = 1.0f - 2.0f*(qx*qx + qz*qz);
    float R12 = 2.0f*(qy*qz - qw*qx);
    float R20 = 2.0f*(qx*qz - qw*qy);
    float R21 = 2.0f*(qy*qz + qw*qx);
    float R22 = 1.0f - 2.0f*(qx*qx + qy*qy);

    float s0 = fabsf(scale[n*3+0]) + 1e-4f;
    float s1 = fabsf(scale[n*3+1]) + 1e-4f;
    float s2 = fabsf(scale[n*3+2]) + 1e-4f;
    float q0 = s0*s0, q1 = s1*s1, q2 = s2*s2;

    // cov3d = R diag(s^2) R^T
    float c00 = R00*R00*q0 + R01*R01*q1 + R02*R02*q2;
    float c01 = R00*R10*q0 + R01*R11*q1 + R02*R12*q2;
    float c02 = R00*R20*q0 + R01*R21*q1 + R02*R22*q2;
    float c11 = R10*R10*q0 + R11*R11*q1 + R12*R12*q2;
    float c12 = R10*R20*q0 + R11*R21*q1 + R12*R22*q2;
    float c22 = R20*R20*q0 + R21*R21*q1 + R22*R22*q2;

    float v00 = c00*M00 + c01*M01 + c02*M02;
    float v01 = c01*M00 + c11*M01 + c12*M02;
    float v02 = c02*M00 + c12*M01 + c22*M02;
    float v10 = c00*M10 + c01*M11 + c02*M12;
    float v11 = c01*M10 + c11*M11 + c12*M12;
    float v12 = c02*M10 + c12*M11 + c22*M12;

    float a  = M00*v00 + M01*v01 + M02*v02 + EPSV;   // cov2d_00  (== Sigma_xx)
    float b  = M00*v10 + M01*v11 + M02*v12;          // cov2d_01
    float cc = M10*v10 + M11*v11 + M12*v12 + EPSV;   // cov2d_11  (== Sigma_yy)

    float det  = a*cc - b*b;
    float idet = 1.0f / det;
    float A = -0.5f * cc * idet;
    float B =  b * idet;
    float C = -0.5f * a  * idet;

    float opa_s = sigmoidf_(opa[n]);
    float L = (z > NEARV) ? logf(opa_s) : -1e30f;   // folded ln(opacity); near-mask -> -inf

    // conservative AABB of {pw + L >= -TAU}: half widths sqrt(2*tau*Sigma_xx/yy)
    float tau = TAU + L;
    float hx, hy;
    if (tau > 0.0f) {
        hx = sqrtf(2.0f * tau * a);
        hy = sqrtf(2.0f * tau * cc);
    } else {
        hx = -1e30f; hy = -1e30f;   // empty box -> always culled
    }

    float cr = sigmoidf_(rgb[n*3+0]);
    float cg = sigmoidf_(rgb[n*3+1]);
    float cb = sigmoidf_(rgb[n*3+2]);

    d_cull[n] = make_float4(u, v, hx, hy);
    d_ga [n]  = make_float4(u, v, A, B);
    d_gb [n]  = make_float4(C, L, cr, cg);
    d_bb [n]  = cb;
    d_key[n]  = r;
}

// ---------------- 2) per-tile cull + local depth-sort + composite ----------------
// grid (NTX, NTY), 128 threads; tile = TW x TH pixels, one thread per pixel.
__global__ void __launch_bounds__(BT) render_kernel(float* __restrict__ out)
{
    __shared__ float kr  [NG];
    __shared__ int   kidx[NG];
    __shared__ int   sidx[NG];
    __shared__ int   scnt;

    int t  = threadIdx.x;
    int tx = blockIdx.x, ty = blockIdx.y;

    if (t == 0) scnt = 0;
    __syncthreads();

    // tile pixel-center bounds in NDC
    const float xmin = (tx*TW        - 63.5f) * (1.0f/128.0f);
    const float xmax = (tx*TW + TW-1 - 63.5f) * (1.0f/128.0f);
    const float ymin = (ty*TH        - 63.5f) * (1.0f/128.0f);
    const float ymax = (ty*TH + TH-1 - 63.5f) * (1.0f/128.0f);

    // ---- cull: AABB vs tile ----
#pragma unroll
    for (int g = t; g < NG; g += BT) {
        float4 cv = d_cull[g];
        bool keep = (cv.x - cv.z <= xmax) && (cv.x + cv.z >= xmin) &&
                    (cv.y - cv.w <= ymax) && (cv.y + cv.w >= ymin);
        if (keep) {
            int slot = atomicAdd(&scnt, 1);
            kr[slot]   = d_key[g];
            kidx[slot] = g;
        }
    }
    __syncthreads();
    int N = scnt;

    // ---- local depth rank-sort (keys are distinct floats) ----
    for (int i = t; i < N; i += BT) {
        float ki = kr[i];
        int c = 0;
        for (int j = 0; j < N; j++) {
            float kj = kr[j];
            c += (kj < ki) || (kj == ki && j < i);
        }
        sidx[c] = kidx[i];
    }
    __syncthreads();

    // ---- composite (front-to-back) ----
    int x = tx*TW + (t & (TW-1));
    int y = ty*TH + (t >> 4);
    float px = (x - 63.5f) * (1.0f/128.0f);
    float py = (y - 63.5f) * (1.0f/128.0f);

    float T = 1.0f, cr = 0.0f, cg = 0.0f, cb = 0.0f;

#pragma unroll 4
    for (int k = 0; k < N; k++) {
        int g = sidx[k];
        float4 ga = __ldg(&d_ga[g]);
        float4 gb = __ldg(&d_gb[g]);
        float dx = px - ga.x;
        float dy = py - ga.y;
        // pw = A dx^2 + B dx dy + C dy^2 + ln(opa)
        float pw = fmaf(fmaf(ga.z, dx, ga.w * dy), dx, fmaf(gb.x * dy, dy, gb.y));
        if (pw > -TAU) {
            float al = fminf(__expf(pw), 0.99f);
            float wg = T * al;
            cr = fmaf(wg, gb.z, cr);
            cg = fmaf(wg, gb.w, cg);
            cb = fmaf(wg, __ldg(&d_bb[g]), cb);
            T -= wg;
        }
    }

    int o = (y * W + x) * 3;
    out[o + 0] = cr;
    out[o + 1] = cg;
    out[o + 2] = cb;
}

extern "C" void kernel_launch(void* const* d_in, const int* in_sizes, int n_in,
                              void* d_out, int out_size)
{
    const float* pos   = (const float*)d_in[0];
    const float* rgb   = (const float*)d_in[1];
    const float* opa   = (const float*)d_in[2];
    const float* quat  = (const float*)d_in[3];
    const float* scale = (const float*)d_in[4];
    const float* rot   = (const float*)d_in[5];
    const float* tran  = (const float*)d_in[6];
    float* out = (float*)d_out;

    prep_kernel<<<NG/256, 256>>>(pos, rgb, opa, quat, scale, rot, tran);
    render_kernel<<<dim3(NTX, NTY), BT>>>(out);
}

// round 3
// speedup vs baseline: 3.0944x; 3.0944x over previous
#include <cuda_runtime.h>
#include <math.h>

#define NG    2048
#define W     128
#define H     128
#define EPSV  1e-4f
#define NEARV 0.3f
#define TW    16          // tile width (px)
#define TH    8           // tile height (px)
#define PPT   (TW*TH)     // 128 pixels per tile
#define NTX   (W/TW)      // 8
#define NTY   (H/TH)      // 16
#define NSUB  8           // depth chunks per block
#define BT    (NSUB*PPT)  // 1024 threads
#define TAU   18.2f       // cull threshold on folded exponent

// ---------------- device scratch ----------------
__device__ float4 d_cull[NG];  // u, v, hx, hy   (conservative AABB half-widths)
__device__ float4 d_ga [NG];   // u, v, A, B     (pw = A dx^2 + B dx dy + C dy^2 + L)
__device__ float4 d_gb [NG];   // C, L, r, g
__device__ float  d_bb [NG];   // b
__device__ float  d_key[NG];   // depth key r (camera-space norm)

__device__ __forceinline__ float sigmoidf_(float x) {
    return 1.0f / (1.0f + expf(-x));
}

// ---------------- 1) per-gaussian preprocessing ----------------
__global__ void prep_kernel(const float* __restrict__ pos,
                            const float* __restrict__ rgb,
                            const float* __restrict__ opa,
                            const float* __restrict__ quat,
                            const float* __restrict__ scale,
                            const float* __restrict__ rot,
                            const float* __restrict__ tran)
{
    int n = blockIdx.x * blockDim.x + threadIdx.x;
    if (n >= NG) return;

    float Rw[9];
#pragma unroll
    for (int i = 0; i < 9; i++) Rw[i] = __ldg(&rot[i]);
    float t0 = __ldg(&tran[0]), t1 = __ldg(&tran[1]), t2 = __ldg(&tran[2]);

    float p0 = pos[n*3+0], p1 = pos[n*3+1], p2 = pos[n*3+2];
    float x = Rw[0]*p0 + Rw[1]*p1 + Rw[2]*p2 + t0;
    float y = Rw[3]*p0 + Rw[4]*p1 + Rw[5]*p2 + t1;
    float z = Rw[6]*p0 + Rw[7]*p1 + Rw[8]*p2 + t2;

    float r = sqrtf(x*x + y*y + z*z);
    float iz  = 1.0f / z;
    float u = x * iz, v = y * iz;
    float iz2 = iz * iz;

    float M00 = iz*Rw[0] - x*iz2*Rw[6];
    float M01 = iz*Rw[1] - x*iz2*Rw[7];
    float M02 = iz*Rw[2] - x*iz2*Rw[8];
    float M10 = iz*Rw[3] - y*iz2*Rw[6];
    float M11 = iz*Rw[4] - y*iz2*Rw[7];
    float M12 = iz*Rw[5] - y*iz2*Rw[8];

    float qw = quat[n*4+0], qx = quat[n*4+1], qy = quat[n*4+2], qz = quat[n*4+3];
    float qn = rsqrtf(qw*qw + qx*qx + qy*qy + qz*qz);
    qw *= qn; qx *= qn; qy *= qn; qz *= qn;
    float R00 = 1.0f - 2.0f*(qy*qy + qz*qz);
    float R01 = 2.0f*(qx*qy - qw*qz);
    float R02 = 2.0f*(qx*qz + qw*qy);
    float R10 = 2.0f*(qx*qy + qw*qz);
    float R11 = 1.0f - 2.0f*(qx*qx + qz*qz);
    float R12 = 2.0f*(qy*qz - qw*qx);
    float R20 = 2.0f*(qx*qz - qw*qy);
    float R21 = 2.0f*(qy*qz + qw*qx);
    float R22 = 1.0f - 2.0f*(qx*qx + qy*qy);

    float s0 = fabsf(scale[n*3+0]) + 1e-4f;
    float s1 = fabsf(scale[n*3+1]) + 1e-4f;
    float s2 = fabsf(scale[n*3+2]) + 1e-4f;
    float q0 = s0*s0, q1 = s1*s1, q2 = s2*s2;

    float c00 = R00*R00*q0 + R01*R01*q1 + R02*R02*q2;
    float c01 = R00*R10*q0 + R01*R11*q1 + R02*R12*q2;
    float c02 = R00*R20*q0 + R01*R21*q1 + R02*R22*q2;
    float c11 = R10*R10*q0 + R11*R11*q1 + R12*R12*q2;
    float c12 = R10*R20*q0 + R11*R21*q1 + R12*R22*q2;
    float c22 = R20*R20*q0 + R21*R21*q1 + R22*R22*q2;

    float v00 = c00*M00 + c01*M01 + c02*M02;
    float v01 = c01*M00 + c11*M01 + c12*M02;
    float v02 = c02*M00 + c12*M01 + c22*M02;
    float v10 = c00*M10 + c01*M11 + c02*M12;
    float v11 = c01*M10 + c11*M11 + c12*M12;
    float v12 = c02*M10 + c12*M11 + c22*M12;

    float a  = M00*v00 + M01*v01 + M02*v02 + EPSV;   // Sigma_xx
    float b  = M00*v10 + M01*v11 + M02*v12;
    float cc = M10*v10 + M11*v11 + M12*v12 + EPSV;   // Sigma_yy

    float det  = a*cc - b*b;
    float idet = 1.0f / det;
    float A = -0.5f * cc * idet;
    float B =  b * idet;
    float C = -0.5f * a  * idet;

    float opa_s = sigmoidf_(opa[n]);
    float L = (z > NEARV) ? logf(opa_s) : -1e30f;

    // conservative AABB of {quad + L >= -TAU}: half widths sqrt(2*tau*Sigma)
    float tau = TAU + L;
    float hx, hy;
    if (tau > 0.0f) {
        hx = sqrtf(2.0f * tau * a);
        hy = sqrtf(2.0f * tau * cc);
    } else {
        hx = -1e30f; hy = -1e30f;   // empty -> always culled
    }

    float cr = sigmoidf_(rgb[n*3+0]);
    float cg = sigmoidf_(rgb[n*3+1]);
    float cb = sigmoidf_(rgb[n*3+2]);

    d_cull[n] = make_float4(u, v, hx, hy);
    d_ga [n]  = make_float4(u, v, A, B);
    d_gb [n]  = make_float4(C, L, cr, cg);
    d_bb [n]  = cb;
    d_key[n]  = r;
}

// ---------------- 2) per-tile cull + sort + chunked composite ----------------
// grid (NTX, NTY), 1024 threads. Tile = 16x8 px. Culled+sorted list split into
// NSUB depth chunks; chunk s composited by threads [s*128,(s+1)*128) over all
// 128 pixels; partials recombined exactly.
extern __shared__ char smx[];

__global__ void __launch_bounds__(BT, 1) render_kernel(float* __restrict__ out)
{
    float4* sga  = (float4*)(smx);                         // 32KB sorted u,v,A,B
    float4* sgb  = (float4*)(smx + 32768);                 // 32KB sorted C,L,r,g
    float4* part = (float4*)(smx + 65536);                 // 16KB [NSUB][PPT]
    float*  kr   = (float* )(smx + 81920);                 //  8KB culled keys
    float*  sbb  = (float* )(smx + 90112);                 //  8KB sorted b
    int*    kidx = (int*  )(smx + 98304);                  //  8KB culled ids
    __shared__ int scnt;

    int t  = threadIdx.x;
    int tx = blockIdx.x, ty = blockIdx.y;

    if (t == 0) scnt = 0;
    __syncthreads();

    const float xmin = (tx*TW        - 63.5f) * (1.0f/128.0f);
    const float xmax = (tx*TW + TW-1 - 63.5f) * (1.0f/128.0f);
    const float ymin = (ty*TH        - 63.5f) * (1.0f/128.0f);
    const float ymax = (ty*TH + TH-1 - 63.5f) * (1.0f/128.0f);

    // ---- cull ----
#pragma unroll
    for (int g = t; g < NG; g += BT) {
        float4 cv = __ldg(&d_cull[g]);
        bool keep = (cv.x - cv.z <= xmax) && (cv.x + cv.z >= xmin) &&
                    (cv.y - cv.w <= ymax) && (cv.y + cv.w >= ymin);
        if (keep) {
            int slot = atomicAdd(&scnt, 1);
            kr[slot]   = __ldg(&d_key[g]);
            kidx[slot] = g;
        }
    }
    __syncthreads();
    int N = scnt;

    // ---- rank sort by depth + gather into smem (sorted order) ----
    for (int i = t; i < N; i += BT) {
        float ki = kr[i];
        int   gi = kidx[i];
        int c = 0;
        for (int j = 0; j < N; j++) {
            float kj = kr[j];
            c += (int)((kj < ki) | ((kj == ki) & (kidx[j] < gi)));
        }
        sga[c] = __ldg(&d_ga[gi]);
        sgb[c] = __ldg(&d_gb[gi]);
        sbb[c] = __ldg(&d_bb[gi]);
    }
    __syncthreads();

    // ---- chunked composite (branch-free; exp underflow handles misses) ----
    int sub = t >> 7;            // 0..7 depth chunk
    int pix = t & (PPT-1);       // 0..127 pixel in tile
    int x = tx*TW + (pix & (TW-1));
    int y = ty*TH + (pix >> 4);
    float px = (x - 63.5f) * (1.0f/128.0f);
    float py = (y - 63.5f) * (1.0f/128.0f);

    int Nc = (N + NSUB - 1) / NSUB;
    int k0 = sub * Nc;
    int k1 = k0 + Nc; if (k1 > N) k1 = N;

    float T = 1.0f, cr = 0.0f, cg = 0.0f, cb = 0.0f;
#pragma unroll 4
    for (int k = k0; k < k1; k++) {
        float4 ga = sga[k];
        float4 gb = sgb[k];
        float dx = px - ga.x;
        float dy = py - ga.y;
        float pw = fmaf(fmaf(ga.z, dx, ga.w * dy), dx, fmaf(gb.x * dy, dy, gb.y));
        float al = fminf(__expf(pw), 0.99f);
        float wg = T * al;
        cr = fmaf(wg, gb.z, cr);
        cg = fmaf(wg, gb.w, cg);
        cb = fmaf(wg, sbb[k], cb);
        T -= wg;
    }
    part[sub * PPT + pix] = make_float4(cr, cg, cb, T);
    __syncthreads();

    // ---- exact recombination: img = sum_s (prod_{t<s} T_t) img_s ----
    if (t < PPT) {
        float P = 1.0f, r = 0.0f, g = 0.0f, b = 0.0f;
#pragma unroll
        for (int s = 0; s < NSUB; s++) {
            float4 q = part[s * PPT + t];
            r = fmaf(P, q.x, r);
            g = fmaf(P, q.y, g);
            b = fmaf(P, q.z, b);
            P *= q.w;
        }
        int xx = tx*TW + (t & (TW-1));
        int yy = ty*TH + (t >> 4);
        int o = (yy * W + xx) * 3;
        out[o + 0] = r;
        out[o + 1] = g;
        out[o + 2] = b;
    }
}

#define RENDER_SMEM (106496)

extern "C" void kernel_launch(void* const* d_in, const int* in_sizes, int n_in,
                              void* d_out, int out_size)
{
    const float* pos   = (const float*)d_in[0];
    const float* rgb   = (const float*)d_in[1];
    const float* opa   = (const float*)d_in[2];
    const float* quat  = (const float*)d_in[3];
    const float* scale = (const float*)d_in[4];
    const float* rot   = (const float*)d_in[5];
    const float* tran  = (const float*)d_in[6];
    float* out = (float*)d_out;

    static int smem_set = 0;
    if (!smem_set) {
        cudaFuncSetAttribute(render_kernel,
                             cudaFuncAttributeMaxDynamicSharedMemorySize,
                             RENDER_SMEM);
        smem_set = 1;
    }

    prep_kernel<<<NG/256, 256>>>(pos, rgb, opa, quat, scale, rot, tran);
    render_kernel<<<dim3(NTX, NTY), BT, RENDER_SMEM>>>(out);
}